// round 16
// baseline (speedup 1.0000x reference)
#include <cuda_runtime.h>

// PersistenceLandscapeEncoder: pairs (32768,2) f32 -> landscapes (5,4096) f32.
//
// tent_i(t) = min(t-b_i, d_i-t) clamped at 0.  With m=(b+d)/2:
//   bucket(m) < bucket(t) => m < t  => value = d - t   (prefix top-5 deaths)
//   bucket(m) > bucket(t) => m > t  => value = t - b   (suffix bot-5 births)
//   bucket(m) = bucket(t)           => evaluated exactly (home bucket)
// Buckets on a FIXED grid [0, 1.6) -> scatter needs NO minmax (chain shrinks).
//
// 3 PDL-chained launches:
//   K1 scatter(fixed buckets) + minmax        128 blk x 128  (no internal dep)
//   K2 per-bucket lists + excl fine scans      32 blk x 128
//   K3 coarse scan + home-bucket + columns     32 blk x 128
// Replay-safe: g_count zeroed in K2 (g_cnt2 stable copy for K3);
//              g_amin/g_amax reset in K3 tail.

#define N_PAIRS 32768
#define RES     4096
#define NB      4096
#define CAP     64
#define NGROUP  128          // NB / 32
#define FIX_HI  1.6f
#define NEGINF  (-3.0e38f)
#define POSINF  (3.0e38f)

__device__ unsigned g_amin = 0xFFFFFFFFu;   // ordered-uint encodings
__device__ unsigned g_amax = 0u;
__device__ int    g_count[NB];              // zero-init; zeroed each run in K2
__device__ int    g_cnt2[NB];               // stable copy for K3
__device__ float2 g_slab[NB * CAP];
__device__ float4 g_Pf4[NB];  __device__ float g_Pf1[NB];  // fine EXCL prefix top5 d
__device__ float4 g_Sf4[NB];  __device__ float g_Sf1[NB];  // fine EXCL suffix bot5 b
__device__ float  g_GT[NGROUP][5];          // group total top-5 d (desc)
__device__ float  g_GB[NGROUP][5];          // group total bot-5 b (asc)

__device__ __forceinline__ unsigned enc(float f) {
    int i = __float_as_int(f);
    return (unsigned)(i ^ ((i >> 31) | 0x80000000));
}
__device__ __forceinline__ float dec(unsigned u) {
    int i = (u & 0x80000000u) ? (int)(u ^ 0x80000000u) : ~(int)u;
    return __int_as_float(i);
}

// ---- sorted 5-list networks (static indices only) --------------------------
__device__ __forceinline__ void merge_desc(
    float& a0, float& a1, float& a2, float& a3, float& a4,
    float b0, float b1, float b2, float b3, float b4)
{
    float m0 = fmaxf(a0, b0);
    float m1 = fmaxf(fmaxf(a1, b1), fminf(a0, b0));
    float m2 = fmaxf(fmaxf(a2, b2), fmaxf(fminf(a0, b1), fminf(a1, b0)));
    float m3 = fmaxf(fmaxf(a3, b3),
               fmaxf(fminf(a0, b2), fmaxf(fminf(a1, b1), fminf(a2, b0))));
    float m4 = fmaxf(fmaxf(a4, b4),
               fmaxf(fmaxf(fminf(a0, b3), fminf(a1, b2)),
                     fmaxf(fminf(a2, b1), fminf(a3, b0))));
    a0 = m0; a1 = m1; a2 = m2; a3 = m3; a4 = m4;
}

__device__ __forceinline__ void merge_asc(
    float& a0, float& a1, float& a2, float& a3, float& a4,
    float b0, float b1, float b2, float b3, float b4)
{
    float m0 = fminf(a0, b0);
    float m1 = fminf(fminf(a1, b1), fmaxf(a0, b0));
    float m2 = fminf(fminf(a2, b2), fminf(fmaxf(a0, b1), fmaxf(a1, b0)));
    float m3 = fminf(fminf(a3, b3),
               fminf(fmaxf(a0, b2), fminf(fmaxf(a1, b1), fmaxf(a2, b0))));
    float m4 = fminf(fminf(a4, b4),
               fminf(fminf(fmaxf(a0, b3), fmaxf(a1, b2)),
                     fminf(fmaxf(a2, b1), fmaxf(a3, b0))));
    a0 = m0; a1 = m1; a2 = m2; a3 = m3; a4 = m4;
}

__device__ __forceinline__ void insert_desc(
    float& t0, float& t1, float& t2, float& t3, float& t4, float v)
{
    if (v > t4) {
        t4 = v;
        if (t4 > t3) { float x = t4; t4 = t3; t3 = x;
          if (t3 > t2) { x = t3; t3 = t2; t2 = x;
            if (t2 > t1) { x = t2; t2 = t1; t1 = x;
              if (t1 > t0) { x = t1; t1 = t0; t0 = x; }
            }
          }
        }
    }
}

__device__ __forceinline__ void insert_asc(
    float& t0, float& t1, float& t2, float& t3, float& t4, float v)
{
    if (v < t4) {
        t4 = v;
        if (t4 < t3) { float x = t4; t4 = t3; t3 = x;
          if (t3 < t2) { x = t3; t3 = t2; t2 = x;
            if (t2 < t1) { x = t2; t2 = t1; t1 = x;
              if (t1 < t0) { x = t1; t1 = t0; t0 = x; }
            }
          }
        }
    }
}

// ---------------------------------------------------------------------------
// K1: fixed-grid scatter + minmax atomics.  128 blocks x 128.  No internal dep.
// ---------------------------------------------------------------------------
__global__ void __launch_bounds__(128) prep_kernel(const float2* __restrict__ pairs) {
    __shared__ float smn[4], smx[4];
    const int tid = threadIdx.x;
    const float4 v = ((const float4*)pairs)[blockIdx.x * 128 + tid];  // (b,d,b,d)
    const float fscale = (float)NB / FIX_HI;

    // scatter both pairs (fixed buckets: independent of minmax)
    {
        float m0 = 0.5f * (v.x + v.y);
        int b0i = min(NB - 1, max(0, (int)(m0 * fscale)));
        int pos0 = atomicAdd(&g_count[b0i], 1);
        if (pos0 < CAP) g_slab[b0i * CAP + pos0] = make_float2(v.x, v.y);

        float m1 = 0.5f * (v.z + v.w);
        int b1i = min(NB - 1, max(0, (int)(m1 * fscale)));
        int pos1 = atomicAdd(&g_count[b1i], 1);
        if (pos1 < CAP) g_slab[b1i * CAP + pos1] = make_float2(v.z, v.w);
    }

    // minmax reduction
    float mn = fminf(v.x, v.z);
    float mx = fmaxf(v.y, v.w);
    #pragma unroll
    for (int off = 16; off >= 1; off >>= 1) {
        mn = fminf(mn, __shfl_xor_sync(0xffffffffu, mn, off));
        mx = fmaxf(mx, __shfl_xor_sync(0xffffffffu, mx, off));
    }
    if ((tid & 31) == 0) { smn[tid >> 5] = mn; smx[tid >> 5] = mx; }
    __syncthreads();
    if (tid < 4) {
        mn = smn[tid]; mx = smx[tid];
        #pragma unroll
        for (int off = 2; off >= 1; off >>= 1) {
            mn = fminf(mn, __shfl_xor_sync(0xfu, mn, off));
            mx = fmaxf(mx, __shfl_xor_sync(0xfu, mx, off));
        }
        if (tid == 0) {
            atomicMin(&g_amin, enc(mn));
            atomicMax(&g_amax, enc(mx));
        }
    }
}

// ---------------------------------------------------------------------------
// K2: warp per 32-bucket group: fine EXCLUSIVE prefix/suffix lists + totals.
//     32 blocks x 128.  Copies counts, zeroes g_count.
// ---------------------------------------------------------------------------
__global__ void __launch_bounds__(128) group_kernel() {
    cudaGridDependencySynchronize();                       // K1 complete

    const int warp = (blockIdx.x * 128 + threadIdx.x) >> 5;  // group 0..127
    const int lane = threadIdx.x & 31;
    const int bkt  = warp * 32 + lane;

    float d0=NEGINF,d1=NEGINF,d2=NEGINF,d3=NEGINF,d4=NEGINF;
    float b0=POSINF,b1=POSINF,b2=POSINF,b3=POSINF,b4=POSINF;
    const int n = min(g_count[bkt], CAP);
    g_cnt2[bkt]  = n;                       // stable copy for K3
    g_count[bkt] = 0;                       // replay-safe reset (sole toucher)
    const float2* s = &g_slab[bkt * CAP];
    for (int k = 0; k < n; k++) {
        float2 p = s[k];
        insert_desc(d0, d1, d2, d3, d4, p.y);
        insert_asc (b0, b1, b2, b3, b4, p.x);
    }

    // inclusive prefix scan of deaths (desc)
    float i0=d0, i1=d1, i2=d2, i3=d3, i4=d4;
    #pragma unroll
    for (int off = 1; off < 32; off <<= 1) {
        float e0 = __shfl_up_sync(0xffffffffu, i0, off);
        float e1 = __shfl_up_sync(0xffffffffu, i1, off);
        float e2 = __shfl_up_sync(0xffffffffu, i2, off);
        float e3 = __shfl_up_sync(0xffffffffu, i3, off);
        float e4 = __shfl_up_sync(0xffffffffu, i4, off);
        if (lane >= off) merge_desc(i0,i1,i2,i3,i4, e0,e1,e2,e3,e4);
    }
    // exclusive prefix = shift inclusive up by one lane
    float p0 = __shfl_up_sync(0xffffffffu, i0, 1);
    float p1 = __shfl_up_sync(0xffffffffu, i1, 1);
    float p2 = __shfl_up_sync(0xffffffffu, i2, 1);
    float p3 = __shfl_up_sync(0xffffffffu, i3, 1);
    float p4 = __shfl_up_sync(0xffffffffu, i4, 1);
    if (lane == 0) { p0=NEGINF; p1=NEGINF; p2=NEGINF; p3=NEGINF; p4=NEGINF; }
    g_Pf4[bkt] = make_float4(p0, p1, p2, p3);
    g_Pf1[bkt] = p4;
    if (lane == 31) {
        g_GT[warp][0]=i0; g_GT[warp][1]=i1; g_GT[warp][2]=i2;
        g_GT[warp][3]=i3; g_GT[warp][4]=i4;
    }

    // inclusive suffix scan of births (asc)
    float u0=b0, u1=b1, u2=b2, u3=b3, u4=b4;
    #pragma unroll
    for (int off = 1; off < 32; off <<= 1) {
        float e0 = __shfl_down_sync(0xffffffffu, u0, off);
        float e1 = __shfl_down_sync(0xffffffffu, u1, off);
        float e2 = __shfl_down_sync(0xffffffffu, u2, off);
        float e3 = __shfl_down_sync(0xffffffffu, u3, off);
        float e4 = __shfl_down_sync(0xffffffffu, u4, off);
        if (lane + off < 32) merge_asc(u0,u1,u2,u3,u4, e0,e1,e2,e3,e4);
    }
    if (lane == 0) {
        g_GB[warp][0]=u0; g_GB[warp][1]=u1; g_GB[warp][2]=u2;
        g_GB[warp][3]=u3; g_GB[warp][4]=u4;
    }
    // exclusive suffix = shift inclusive down by one lane
    float q0 = __shfl_down_sync(0xffffffffu, u0, 1);
    float q1 = __shfl_down_sync(0xffffffffu, u1, 1);
    float q2 = __shfl_down_sync(0xffffffffu, u2, 1);
    float q3 = __shfl_down_sync(0xffffffffu, u3, 1);
    float q4 = __shfl_down_sync(0xffffffffu, u4, 1);
    if (lane == 31) { q0=POSINF; q1=POSINF; q2=POSINF; q3=POSINF; q4=POSINF; }
    g_Sf4[bkt] = make_float4(q0, q1, q2, q3);
    g_Sf1[bkt] = q4;
}

// ---------------------------------------------------------------------------
// K3: 32 blocks x 128: redundant coarse scan (2 barriers) + home bucket +
//     128 columns per block.  Resets g_amin/g_amax.
// ---------------------------------------------------------------------------
__global__ void __launch_bounds__(128) landscape_kernel(float* __restrict__ out)
{
    __shared__ float sPc[NGROUP][5], sSc[NGROUP][5];
    __shared__ float wtP[4][5], wtS[4][5];
    const int tid  = threadIdx.x;        // == group id 0..127 for the scan
    const int w    = tid >> 5;
    const int lane = tid & 31;

    cudaGridDependencySynchronize();                       // K2 complete

    const float tmin = dec(g_amin);
    const float tmax = dec(g_amax);
    const float dt   = fmaxf(tmax - tmin, 1e-30f) / (float)(RES - 1);
    const float fscale = (float)NB / FIX_HI;

    // ---- coarse exclusive prefix over shifted GT (A'[g] = GT[g-1]) ----
    float a0=NEGINF,a1=NEGINF,a2=NEGINF,a3=NEGINF,a4=NEGINF;
    if (tid > 0) { a0=g_GT[tid-1][0]; a1=g_GT[tid-1][1]; a2=g_GT[tid-1][2];
                   a3=g_GT[tid-1][3]; a4=g_GT[tid-1][4]; }
    #pragma unroll
    for (int off = 1; off < 32; off <<= 1) {
        float e0 = __shfl_up_sync(0xffffffffu, a0, off);
        float e1 = __shfl_up_sync(0xffffffffu, a1, off);
        float e2 = __shfl_up_sync(0xffffffffu, a2, off);
        float e3 = __shfl_up_sync(0xffffffffu, a3, off);
        float e4 = __shfl_up_sync(0xffffffffu, a4, off);
        if (lane >= off) merge_desc(a0,a1,a2,a3,a4, e0,e1,e2,e3,e4);
    }
    if (lane == 31) { wtP[w][0]=a0; wtP[w][1]=a1; wtP[w][2]=a2;
                      wtP[w][3]=a3; wtP[w][4]=a4; }

    // ---- coarse exclusive suffix over shifted GB (A''[g] = GB[g+1]) ----
    float c0=POSINF,c1=POSINF,c2=POSINF,c3=POSINF,c4=POSINF;
    if (tid < NGROUP - 1) { c0=g_GB[tid+1][0]; c1=g_GB[tid+1][1];
                            c2=g_GB[tid+1][2]; c3=g_GB[tid+1][3];
                            c4=g_GB[tid+1][4]; }
    #pragma unroll
    for (int off = 1; off < 32; off <<= 1) {
        float e0 = __shfl_down_sync(0xffffffffu, c0, off);
        float e1 = __shfl_down_sync(0xffffffffu, c1, off);
        float e2 = __shfl_down_sync(0xffffffffu, c2, off);
        float e3 = __shfl_down_sync(0xffffffffu, c3, off);
        float e4 = __shfl_down_sync(0xffffffffu, c4, off);
        if (lane + off < 32) merge_asc(c0,c1,c2,c3,c4, e0,e1,e2,e3,e4);
    }
    if (lane == 0) { wtS[w][0]=c0; wtS[w][1]=c1; wtS[w][2]=c2;
                     wtS[w][3]=c3; wtS[w][4]=c4; }
    __syncthreads();

    // ---- cross-warp fixups ----
    #pragma unroll
    for (int q = 0; q < 3; q++)
        if (q < w)
            merge_desc(a0,a1,a2,a3,a4,
                       wtP[q][0], wtP[q][1], wtP[q][2], wtP[q][3], wtP[q][4]);
    #pragma unroll
    for (int q = 1; q < 4; q++)
        if (q > w)
            merge_asc(c0,c1,c2,c3,c4,
                      wtS[q][0], wtS[q][1], wtS[q][2], wtS[q][3], wtS[q][4]);
    sPc[tid][0]=a0; sPc[tid][1]=a1; sPc[tid][2]=a2; sPc[tid][3]=a3; sPc[tid][4]=a4;
    sSc[tid][0]=c0; sSc[tid][1]=c1; sSc[tid][2]=c2; sSc[tid][3]=c3; sSc[tid][4]=c4;
    __syncthreads();

    // ---- per-column assembly: 128 columns per block ----
    const int j = blockIdx.x * 128 + tid;          // column 0..4095
    const float t = tmin + (float)j * dt;
    const int hb = min(NB - 1, max(0, (int)(t * fscale)));
    const int gp = hb >> 5;

    // home bucket: exact tents (top5 init 0 => clamp built in)
    float h0=0.0f, h1=0.0f, h2=0.0f, h3=0.0f, h4=0.0f;
    {
        const int n2 = g_cnt2[hb];
        const float2* s = &g_slab[hb * CAP];
        for (int k = 0; k < n2; k++) {
            float2 p = s[k];
            float v = fminf(t - p.x, p.y - t);
            insert_desc(h0, h1, h2, h3, h4, v);
        }
    }

    // prefix side: buckets < hb  (fine excl within group + coarse excl)
    float4 pf = g_Pf4[hb]; float pf4 = g_Pf1[hb];
    float p0=pf.x, p1=pf.y, p2=pf.z, p3=pf.w, p4=pf4;
    merge_desc(p0,p1,p2,p3,p4,
               sPc[gp][0], sPc[gp][1], sPc[gp][2], sPc[gp][3], sPc[gp][4]);

    // suffix side: buckets > hb
    float4 sf = g_Sf4[hb]; float sf4 = g_Sf1[hb];
    float s0=sf.x, s1=sf.y, s2=sf.z, s3=sf.w, s4=sf4;
    merge_asc(s0,s1,s2,s3,s4,
              sSc[gp][0], sSc[gp][1], sSc[gp][2], sSc[gp][3], sSc[gp][4]);

    // transform + final merges
    p0 = fmaxf(p0 - t, 0.0f); p1 = fmaxf(p1 - t, 0.0f); p2 = fmaxf(p2 - t, 0.0f);
    p3 = fmaxf(p3 - t, 0.0f); p4 = fmaxf(p4 - t, 0.0f);
    merge_desc(h0,h1,h2,h3,h4, p0,p1,p2,p3,p4);
    float q0 = fmaxf(t - s0, 0.0f), q1 = fmaxf(t - s1, 0.0f);
    float q2 = fmaxf(t - s2, 0.0f), q3 = fmaxf(t - s3, 0.0f);
    float q4 = fmaxf(t - s4, 0.0f);
    merge_desc(h0,h1,h2,h3,h4, q0,q1,q2,q3,q4);

    out[0 * RES + j] = h0;
    out[1 * RES + j] = h1;
    out[2 * RES + j] = h2;
    out[3 * RES + j] = h3;
    out[4 * RES + j] = h4;

    // replay-safe reset of the atomic minmax (consumed above)
    if (blockIdx.x == 0 && tid == 0) {
        g_amin = 0xFFFFFFFFu;
        g_amax = 0u;
    }
}

// ---------------------------------------------------------------------------
template <typename F, typename... Args>
static void launch_pdl(F kernel, dim3 grid, dim3 block, Args... args) {
    cudaLaunchConfig_t cfg = {};
    cfg.gridDim = grid;
    cfg.blockDim = block;
    cfg.dynamicSmemBytes = 0;
    cfg.stream = 0;                       // legacy default stream (captured)
    cudaLaunchAttribute attr[1];
    attr[0].id = cudaLaunchAttributeProgrammaticStreamSerialization;
    attr[0].val.programmaticStreamSerializationAllowed = 1;
    cfg.attrs = attr;
    cfg.numAttrs = 1;
    cudaLaunchKernelEx(&cfg, kernel, args...);
}

extern "C" void kernel_launch(void* const* d_in, const int* in_sizes, int n_in,
                              void* d_out, int out_size) {
    const float2* pairs = (const float2*)d_in[0];
    float* out = (float*)d_out;

    prep_kernel<<<N_PAIRS / 2 / 128, 128>>>(pairs);                 // 128 blocks
    launch_pdl(group_kernel,     dim3(NB / 32 / 4), dim3(128));     // 32 blocks
    launch_pdl(landscape_kernel, dim3(RES / 128),   dim3(128), out);// 32 blocks
}

// round 17
// speedup vs baseline: 1.2236x; 1.2236x over previous
#include <cuda_runtime.h>

// PersistenceLandscapeEncoder: pairs (32768,2) f32 -> landscapes (5,4096) f32.
//
// tent_i(t) = min(t-b_i, d_i-t) clamped at 0.  With m=(b+d)/2:
//   m <  t  ->  value = d - t ;  m >= t -> value = t - b
// Buckets ALIGNED to the t-grid (4096).  Column j:
//   top5 = merge( {prefixTop5d(buckets<j) - t}+ , {t - suffixBot5b(buckets>=j)}+ )
//
// 4 launches, PDL-chained; each producer fires
// cudaTriggerProgrammaticLaunchCompletion() right after its last global write
// so the consumer's cudaGridDependencySynchronize() releases before teardown.
//   K1 minmax    128 blk x 128      K2 scatter  128 blk x 128 (PDL preload)
//   K3 group      32 blk x 128      K4 coarse+columns  32 blk x 128
// Replay-safe: g_count reset in K3; g_amin/g_amax reset in K4 tail.

#define N_PAIRS 32768
#define RES     4096
#define NB      4096
#define CAP     64
#define NGROUP  128          // NB / 32
#define NEGINF  (-3.0e38f)
#define POSINF  (3.0e38f)

__device__ unsigned g_amin = 0xFFFFFFFFu;   // ordered-uint encodings
__device__ unsigned g_amax = 0u;
__device__ float  g_tmin, g_dt;
__device__ int    g_count[NB];              // zero-init; K3 re-zeroes
__device__ float2 g_slab[NB * CAP];
__device__ float4 g_Pf4[NB];  __device__ float g_Pf1[NB];  // excl prefix top5 d
__device__ float4 g_Sf4[NB];  __device__ float g_Sf1[NB];  // incl suffix bot5 b
__device__ float  g_GT[NGROUP][5];   // group total top-5 d (desc)
__device__ float  g_GB[NGROUP][5];   // group total bot-5 b (asc)

__device__ __forceinline__ unsigned enc(float f) {
    int i = __float_as_int(f);
    return (unsigned)(i ^ ((i >> 31) | 0x80000000));
}
__device__ __forceinline__ float dec(unsigned u) {
    int i = (u & 0x80000000u) ? (int)(u ^ 0x80000000u) : ~(int)u;
    return __int_as_float(i);
}

// ---- sorted 5-list networks (static indices only) --------------------------
__device__ __forceinline__ void merge_desc(
    float& a0, float& a1, float& a2, float& a3, float& a4,
    float b0, float b1, float b2, float b3, float b4)
{
    float m0 = fmaxf(a0, b0);
    float m1 = fmaxf(fmaxf(a1, b1), fminf(a0, b0));
    float m2 = fmaxf(fmaxf(a2, b2), fmaxf(fminf(a0, b1), fminf(a1, b0)));
    float m3 = fmaxf(fmaxf(a3, b3),
               fmaxf(fminf(a0, b2), fmaxf(fminf(a1, b1), fminf(a2, b0))));
    float m4 = fmaxf(fmaxf(a4, b4),
               fmaxf(fmaxf(fminf(a0, b3), fminf(a1, b2)),
                     fmaxf(fminf(a2, b1), fminf(a3, b0))));
    a0 = m0; a1 = m1; a2 = m2; a3 = m3; a4 = m4;
}

__device__ __forceinline__ void merge_asc(
    float& a0, float& a1, float& a2, float& a3, float& a4,
    float b0, float b1, float b2, float b3, float b4)
{
    float m0 = fminf(a0, b0);
    float m1 = fminf(fminf(a1, b1), fmaxf(a0, b0));
    float m2 = fminf(fminf(a2, b2), fminf(fmaxf(a0, b1), fmaxf(a1, b0)));
    float m3 = fminf(fminf(a3, b3),
               fminf(fmaxf(a0, b2), fminf(fmaxf(a1, b1), fmaxf(a2, b0))));
    float m4 = fminf(fminf(a4, b4),
               fminf(fminf(fmaxf(a0, b3), fmaxf(a1, b2)),
                     fminf(fmaxf(a2, b1), fmaxf(a3, b0))));
    a0 = m0; a1 = m1; a2 = m2; a3 = m3; a4 = m4;
}

__device__ __forceinline__ void insert_desc(
    float& t0, float& t1, float& t2, float& t3, float& t4, float v)
{
    if (v > t4) {
        t4 = v;
        if (t4 > t3) { float x = t4; t4 = t3; t3 = x;
          if (t3 > t2) { x = t3; t3 = t2; t2 = x;
            if (t2 > t1) { x = t2; t2 = t1; t1 = x;
              if (t1 > t0) { x = t1; t1 = t0; t0 = x; }
            }
          }
        }
    }
}

__device__ __forceinline__ void insert_asc(
    float& t0, float& t1, float& t2, float& t3, float& t4, float v)
{
    if (v < t4) {
        t4 = v;
        if (t4 < t3) { float x = t4; t4 = t3; t3 = x;
          if (t3 < t2) { x = t3; t3 = t2; t2 = x;
            if (t2 < t1) { x = t2; t2 = t1; t1 = x;
              if (t1 < t0) { x = t1; t1 = t0; t0 = x; }
            }
          }
        }
    }
}

// ---------------------------------------------------------------------------
// K1: wide minmax -> atomic encoded min/max.  128 blocks x 128.
// ---------------------------------------------------------------------------
__global__ void __launch_bounds__(128) minmax_kernel(const float2* __restrict__ pairs) {
    __shared__ float smn[4], smx[4];
    const int tid = threadIdx.x;
    const float4 v = ((const float4*)pairs)[blockIdx.x * 128 + tid];  // (b,d,b,d)
    float mn = fminf(v.x, v.z);
    float mx = fmaxf(v.y, v.w);
    #pragma unroll
    for (int off = 16; off >= 1; off >>= 1) {
        mn = fminf(mn, __shfl_xor_sync(0xffffffffu, mn, off));
        mx = fmaxf(mx, __shfl_xor_sync(0xffffffffu, mx, off));
    }
    if ((tid & 31) == 0) { smn[tid >> 5] = mn; smx[tid >> 5] = mx; }
    __syncthreads();
    if (tid < 4) {
        mn = smn[tid]; mx = smx[tid];
        #pragma unroll
        for (int off = 2; off >= 1; off >>= 1) {
            mn = fminf(mn, __shfl_xor_sync(0xfu, mn, off));
            mx = fmaxf(mx, __shfl_xor_sync(0xfu, mx, off));
        }
        if (tid == 0) {
            atomicMin(&g_amin, enc(mn));
            atomicMax(&g_amax, enc(mx));
        }
    }
    // last global write done -> release the dependent launch early
    cudaTriggerProgrammaticLaunchCompletion();
}

// ---------------------------------------------------------------------------
// K2: scatter.  PDL: load pairs + midpoints BEFORE grid sync.  128 blk x 128.
// ---------------------------------------------------------------------------
__global__ void __launch_bounds__(128) scatter_kernel(const float2* __restrict__ pairs) {
    const int i = blockIdx.x * 128 + threadIdx.x;
    const float4 v = ((const float4*)pairs)[i];            // independent preamble
    const float m0 = 0.5f * (v.x + v.y);
    const float m1 = 0.5f * (v.z + v.w);

    cudaGridDependencySynchronize();                       // wait for minmax

    const float tmin = dec(g_amin);
    const float tmax = dec(g_amax);
    const float span = fmaxf(tmax - tmin, 1e-30f);
    const float scale = (float)(RES - 1) / span;
    if (i == 0) {
        g_tmin = tmin;
        g_dt   = span / (float)(RES - 1);
    }
    int b0i = min(NB - 1, max(0, (int)((m0 - tmin) * scale)));
    int pos0 = atomicAdd(&g_count[b0i], 1);
    if (pos0 < CAP) g_slab[b0i * CAP + pos0] = make_float2(v.x, v.y);

    int b1i = min(NB - 1, max(0, (int)((m1 - tmin) * scale)));
    int pos1 = atomicAdd(&g_count[b1i], 1);
    if (pos1 < CAP) g_slab[b1i * CAP + pos1] = make_float2(v.z, v.w);

    // last global write done -> release the dependent launch early
    cudaTriggerProgrammaticLaunchCompletion();
}

// ---------------------------------------------------------------------------
// K3: warp per 32-bucket group: fine lists + shfl scans.  32 blk x 128.
// ---------------------------------------------------------------------------
__global__ void __launch_bounds__(128) group_kernel() {
    cudaGridDependencySynchronize();                       // ramp overlapped

    const int warp = (blockIdx.x * 128 + threadIdx.x) >> 5;  // group 0..127
    const int lane = threadIdx.x & 31;
    const int bkt  = warp * 32 + lane;

    float d0=NEGINF,d1=NEGINF,d2=NEGINF,d3=NEGINF,d4=NEGINF;
    float b0=POSINF,b1=POSINF,b2=POSINF,b3=POSINF,b4=POSINF;
    const int n = min(g_count[bkt], CAP);
    g_count[bkt] = 0;                       // replay-safe reset (sole toucher)
    const float2* s = &g_slab[bkt * CAP];
    for (int k = 0; k < n; k++) {
        float2 p = s[k];
        insert_desc(d0, d1, d2, d3, d4, p.y);
        insert_asc (b0, b1, b2, b3, b4, p.x);
    }

    // inclusive prefix scan of deaths (desc)
    float i0=d0, i1=d1, i2=d2, i3=d3, i4=d4;
    #pragma unroll
    for (int off = 1; off < 32; off <<= 1) {
        float e0 = __shfl_up_sync(0xffffffffu, i0, off);
        float e1 = __shfl_up_sync(0xffffffffu, i1, off);
        float e2 = __shfl_up_sync(0xffffffffu, i2, off);
        float e3 = __shfl_up_sync(0xffffffffu, i3, off);
        float e4 = __shfl_up_sync(0xffffffffu, i4, off);
        if (lane >= off) merge_desc(i0,i1,i2,i3,i4, e0,e1,e2,e3,e4);
    }
    float p0 = __shfl_up_sync(0xffffffffu, i0, 1);
    float p1 = __shfl_up_sync(0xffffffffu, i1, 1);
    float p2 = __shfl_up_sync(0xffffffffu, i2, 1);
    float p3 = __shfl_up_sync(0xffffffffu, i3, 1);
    float p4 = __shfl_up_sync(0xffffffffu, i4, 1);
    if (lane == 0) { p0=NEGINF; p1=NEGINF; p2=NEGINF; p3=NEGINF; p4=NEGINF; }
    g_Pf4[bkt] = make_float4(p0, p1, p2, p3);
    g_Pf1[bkt] = p4;
    if (lane == 31) {
        g_GT[warp][0]=i0; g_GT[warp][1]=i1; g_GT[warp][2]=i2;
        g_GT[warp][3]=i3; g_GT[warp][4]=i4;
    }

    // inclusive suffix scan of births (asc)
    float u0=b0, u1=b1, u2=b2, u3=b3, u4=b4;
    #pragma unroll
    for (int off = 1; off < 32; off <<= 1) {
        float e0 = __shfl_down_sync(0xffffffffu, u0, off);
        float e1 = __shfl_down_sync(0xffffffffu, u1, off);
        float e2 = __shfl_down_sync(0xffffffffu, u2, off);
        float e3 = __shfl_down_sync(0xffffffffu, u3, off);
        float e4 = __shfl_down_sync(0xffffffffu, u4, off);
        if (lane + off < 32) merge_asc(u0,u1,u2,u3,u4, e0,e1,e2,e3,e4);
    }
    g_Sf4[bkt] = make_float4(u0, u1, u2, u3);
    g_Sf1[bkt] = u4;
    if (lane == 0) {
        g_GB[warp][0]=u0; g_GB[warp][1]=u1; g_GB[warp][2]=u2;
        g_GB[warp][3]=u3; g_GB[warp][4]=u4;
    }
    // last global write done -> release the dependent launch early
    cudaTriggerProgrammaticLaunchCompletion();
}

// ---------------------------------------------------------------------------
// K4: 32 blocks x 128: redundant coarse scan (both directions in the same
//     128 threads, 2 barriers) + 128 columns per block.
// ---------------------------------------------------------------------------
__global__ void __launch_bounds__(128) landscape_kernel(float* __restrict__ out)
{
    __shared__ float sPc[NGROUP][5], sSc[NGROUP][5];
    __shared__ float wtP[4][5], wtS[4][5];
    const int tid  = threadIdx.x;        // == group id 0..127
    const int w    = tid >> 5;
    const int lane = tid & 31;

    cudaGridDependencySynchronize();                       // ramp overlapped

    // ---- prefix scan over shifted GT (A'[g] = GT[g-1]) ----
    float a0=NEGINF,a1=NEGINF,a2=NEGINF,a3=NEGINF,a4=NEGINF;
    if (tid > 0) { a0=g_GT[tid-1][0]; a1=g_GT[tid-1][1]; a2=g_GT[tid-1][2];
                   a3=g_GT[tid-1][3]; a4=g_GT[tid-1][4]; }
    #pragma unroll
    for (int off = 1; off < 32; off <<= 1) {
        float e0 = __shfl_up_sync(0xffffffffu, a0, off);
        float e1 = __shfl_up_sync(0xffffffffu, a1, off);
        float e2 = __shfl_up_sync(0xffffffffu, a2, off);
        float e3 = __shfl_up_sync(0xffffffffu, a3, off);
        float e4 = __shfl_up_sync(0xffffffffu, a4, off);
        if (lane >= off) merge_desc(a0,a1,a2,a3,a4, e0,e1,e2,e3,e4);
    }
    if (lane == 31) { wtP[w][0]=a0; wtP[w][1]=a1; wtP[w][2]=a2;
                      wtP[w][3]=a3; wtP[w][4]=a4; }

    // ---- suffix scan over shifted GB (A''[g] = GB[g+1]) ----
    float c0=POSINF,c1=POSINF,c2=POSINF,c3=POSINF,c4=POSINF;
    if (tid < NGROUP - 1) { c0=g_GB[tid+1][0]; c1=g_GB[tid+1][1];
                            c2=g_GB[tid+1][2]; c3=g_GB[tid+1][3];
                            c4=g_GB[tid+1][4]; }
    #pragma unroll
    for (int off = 1; off < 32; off <<= 1) {
        float e0 = __shfl_down_sync(0xffffffffu, c0, off);
        float e1 = __shfl_down_sync(0xffffffffu, c1, off);
        float e2 = __shfl_down_sync(0xffffffffu, c2, off);
        float e3 = __shfl_down_sync(0xffffffffu, c3, off);
        float e4 = __shfl_down_sync(0xffffffffu, c4, off);
        if (lane + off < 32) merge_asc(c0,c1,c2,c3,c4, e0,e1,e2,e3,e4);
    }
    if (lane == 0) { wtS[w][0]=c0; wtS[w][1]=c1; wtS[w][2]=c2;
                     wtS[w][3]=c3; wtS[w][4]=c4; }
    __syncthreads();

    // ---- cross-warp fixups ----
    #pragma unroll
    for (int q = 0; q < 3; q++)
        if (q < w)
            merge_desc(a0,a1,a2,a3,a4,
                       wtP[q][0], wtP[q][1], wtP[q][2], wtP[q][3], wtP[q][4]);
    #pragma unroll
    for (int q = 1; q < 4; q++)
        if (q > w)
            merge_asc(c0,c1,c2,c3,c4,
                      wtS[q][0], wtS[q][1], wtS[q][2], wtS[q][3], wtS[q][4]);
    sPc[tid][0]=a0; sPc[tid][1]=a1; sPc[tid][2]=a2; sPc[tid][3]=a3; sPc[tid][4]=a4;
    sSc[tid][0]=c0; sSc[tid][1]=c1; sSc[tid][2]=c2; sSc[tid][3]=c3; sSc[tid][4]=c4;
    __syncthreads();

    // ---- per-column assembly: 128 columns per block ----
    const int j = blockIdx.x * 128 + tid;          // column 0..4095
    const float t = g_tmin + (float)j * g_dt;
    const int g = j >> 5;

    float4 pf = g_Pf4[j]; float pf4 = g_Pf1[j];
    float p0=pf.x, p1=pf.y, p2=pf.z, p3=pf.w, p4=pf4;
    merge_desc(p0,p1,p2,p3,p4,
               sPc[g][0], sPc[g][1], sPc[g][2], sPc[g][3], sPc[g][4]);

    float4 sf = g_Sf4[j]; float sf4 = g_Sf1[j];
    float s0=sf.x, s1=sf.y, s2=sf.z, s3=sf.w, s4=sf4;
    merge_asc(s0,s1,s2,s3,s4,
              sSc[g][0], sSc[g][1], sSc[g][2], sSc[g][3], sSc[g][4]);

    p0 = fmaxf(p0 - t, 0.0f); p1 = fmaxf(p1 - t, 0.0f); p2 = fmaxf(p2 - t, 0.0f);
    p3 = fmaxf(p3 - t, 0.0f); p4 = fmaxf(p4 - t, 0.0f);
    float q0 = fmaxf(t - s0, 0.0f), q1 = fmaxf(t - s1, 0.0f);
    float q2 = fmaxf(t - s2, 0.0f), q3 = fmaxf(t - s3, 0.0f);
    float q4 = fmaxf(t - s4, 0.0f);
    merge_desc(p0,p1,p2,p3,p4, q0,q1,q2,q3,q4);

    out[0 * RES + j] = p0;
    out[1 * RES + j] = p1;
    out[2 * RES + j] = p2;
    out[3 * RES + j] = p3;
    out[4 * RES + j] = p4;

    // replay-safe reset of the atomic minmax (K2 consumed them this run)
    if (blockIdx.x == 0 && tid == 0) {
        g_amin = 0xFFFFFFFFu;
        g_amax = 0u;
    }
}

// ---------------------------------------------------------------------------
template <typename F, typename... Args>
static void launch_pdl(F kernel, dim3 grid, dim3 block, Args... args) {
    cudaLaunchConfig_t cfg = {};
    cfg.gridDim = grid;
    cfg.blockDim = block;
    cfg.dynamicSmemBytes = 0;
    cfg.stream = 0;                       // legacy default stream (captured)
    cudaLaunchAttribute attr[1];
    attr[0].id = cudaLaunchAttributeProgrammaticStreamSerialization;
    attr[0].val.programmaticStreamSerializationAllowed = 1;
    cfg.attrs = attr;
    cfg.numAttrs = 1;
    cudaLaunchKernelEx(&cfg, kernel, args...);
}

extern "C" void kernel_launch(void* const* d_in, const int* in_sizes, int n_in,
                              void* d_out, int out_size) {
    const float2* pairs = (const float2*)d_in[0];
    float* out = (float*)d_out;

    minmax_kernel<<<N_PAIRS / 2 / 128, 128>>>(pairs);              // 128 blocks
    launch_pdl(scatter_kernel,   dim3(N_PAIRS / 2 / 128), dim3(128), pairs);
    launch_pdl(group_kernel,     dim3(NB / 32 / 4),       dim3(128));       // 32 blk
    launch_pdl(landscape_kernel, dim3(RES / 128),         dim3(128), out);  // 32 blk
}